// round 9
// baseline (speedup 1.0000x reference)
#include <cuda_runtime.h>
#include <math.h>

#define V 50000
#define E 5000
#define E4 (E / 4)          // 1250 uint4 per H row
#define VCH 512             // v-chunk per CTA.y (all chunks incl. tail %8==0)
#define NVC 98              // 98*512 = 50176 >= V
#define NQT 10              // uint4 tiles: 10*128 = 1280 >= 1250
#define CAP 1536            // per-edge list capacity (deg ~ 1001 +- 31)
#define GPART 4             // warps cooperating per edge in gather
#define TAUF 0.5f
#define EPSF 1e-8f

// Scratch (__device__ globals; allocation-free rule)
__device__ __align__(16) float g_P[(size_t)V * 32];   // packed softmax [v][0..15]=ps,[16..31]=pt
__device__ int   g_cnt[E];                            // per-edge nonzero count (= deg_e)
__device__ __align__(16) int g_list[(size_t)E * CAP]; // per-edge vertex lists (unordered)
__device__ float g_Ssum[(size_t)E * 32];              // [e][c] channel sums (atomic-combined)
__device__ float g_Sdeg[E];                           // deg_e (float)
__device__ float g_acc[2];                            // {kl_sum, mask_count}
__device__ int   g_not_int01;                         // mask-dtype detection flags
__device__ int   g_not_f01;

// ---------------------------------------------------------------------------
// Kernel 1: softmax over C=16 for both preds (packed) + zero per-replay state.
// ---------------------------------------------------------------------------
__device__ __forceinline__ void softmax16(const float4* __restrict__ src,
                                          float4* __restrict__ dst) {
    float4 a[4];
#pragma unroll
    for (int i = 0; i < 4; i++) a[i] = src[i];
    float* x = reinterpret_cast<float*>(a);
    float m = x[0];
#pragma unroll
    for (int i = 1; i < 16; i++) m = fmaxf(m, x[i]);
    float s = 0.f;
#pragma unroll
    for (int i = 0; i < 16; i++) { float e = expf(x[i] - m); x[i] = e; s += e; }
    float r = 1.0f / s;
#pragma unroll
    for (int i = 0; i < 16; i++) x[i] *= r;
#pragma unroll
    for (int i = 0; i < 4; i++) dst[i] = a[i];
}

__global__ void softmax_kernel(const float* __restrict__ pred_s,
                               const float* __restrict__ pred_t) {
    int v = blockIdx.x * blockDim.x + threadIdx.x;
    int nthr = gridDim.x * blockDim.x;
    for (int i = v; i < E; i += nthr) g_cnt[i] = 0;
    for (int i = v; i < 32 * E; i += nthr) g_Ssum[i] = 0.f;
    if (v == 0) { g_acc[0] = 0.f; g_acc[1] = 0.f; g_not_int01 = 0; g_not_f01 = 0; }
    if (v >= V) return;
    float4* dst = reinterpret_cast<float4*>(g_P + (size_t)v * 32);
    softmax16(reinterpret_cast<const float4*>(pred_s + (size_t)v * 16), dst);
    softmax16(reinterpret_cast<const float4*>(pred_t + (size_t)v * 16), dst + 4);
}

// ---------------------------------------------------------------------------
// Kernel 1b: detect e_mask storage dtype (uint8 vs int32 vs float32).
// ---------------------------------------------------------------------------
__global__ void detect_mask_kernel(const unsigned int* __restrict__ mask_w) {
    int i = blockIdx.x * blockDim.x + threadIdx.x;
    if (i >= E / 4) return;
    unsigned int w = mask_w[i];
    if (w > 1u) atomicOr(&g_not_int01, 1);
    if (w != 0u && w != 0x3f800000u) atomicOr(&g_not_f01, 1);
}

// ---------------------------------------------------------------------------
// Kernel 2 (pass 1): the 1 GB stream, vectorized. grid (NQT, NVC), 128 thr.
// Each lane owns 4 consecutive edges via one uint4 load (512 B per warp-LDG,
// 8-deep row prefetch -> 4 KB in flight per warp). H is binary, so the
// nonzero test is an integer OR over 4 words (one ISETP, taken ~7.8%); the
// rare path records vertex indices into per-edge lists.
// ---------------------------------------------------------------------------
__global__ void __launch_bounds__(128) build_kernel(const float* __restrict__ H) {
    const int q = blockIdx.x * 128 + threadIdx.x;   // uint4 index within row
    const bool qv = (q < E4);
    const int qc = qv ? q : 0;
    const int v0 = blockIdx.y * VCH;
    const int v1 = min(v0 + VCH, V);                // chunk length always %8 == 0

    const uint4* __restrict__ Hp =
        reinterpret_cast<const uint4*>(H) + (size_t)v0 * E4 + qc;

    for (int v = v0; v < v1; v += 8, Hp += (size_t)8 * E4) {
        uint4 h[8];
#pragma unroll
        for (int u = 0; u < 8; u++)                 // batch-issued, 4 KB/warp in flight
            h[u] = __ldg(Hp + (size_t)u * E4);
#pragma unroll
        for (int u = 0; u < 8; u++) {
            unsigned nz = (h[u].x | h[u].y) | (h[u].z | h[u].w);
            if (qv && nz) {                         // ~7.8% taken per lane-row
                const int eb = 4 * q;
                const int vv = v + u;
                if (h[u].x) { int p = atomicAdd(&g_cnt[eb + 0], 1); if (p < CAP) g_list[(size_t)(eb + 0) * CAP + p] = vv; }
                if (h[u].y) { int p = atomicAdd(&g_cnt[eb + 1], 1); if (p < CAP) g_list[(size_t)(eb + 1) * CAP + p] = vv; }
                if (h[u].z) { int p = atomicAdd(&g_cnt[eb + 2], 1); if (p < CAP) g_list[(size_t)(eb + 2) * CAP + p] = vv; }
                if (h[u].w) { int p = atomicAdd(&g_cnt[eb + 3], 1); if (p < CAP) g_list[(size_t)(eb + 3) * CAP + p] = vv; }
            }
        }
    }
}

// ---------------------------------------------------------------------------
// Kernel 3 (pass 2): gather. GPART=4 warps per edge, lane = channel.
// Warp p walks every-4th group of 8 list entries (int4-aligned), loads 8
// uniform 128B P rows per group, accumulates in 4 rotating FADD chains,
// and combines via one atomicAdd per (e,c). 32-bit address math throughout.
// ---------------------------------------------------------------------------
__global__ void __launch_bounds__(128) gather_kernel() {
    const int gw   = (blockIdx.x * 128 + threadIdx.x) >> 5;  // global warp id
    const int lane = threadIdx.x & 31;                       // channel
    const int e    = gw >> 2;
    const int part = gw & (GPART - 1);
    if (e >= E) return;
    const int cnt = min(g_cnt[e], CAP);
    const int* __restrict__ lst = g_list + (size_t)e * CAP;
    const float* __restrict__ Pb = g_P + lane;

    float s0 = 0.f, s1 = 0.f, s2 = 0.f, s3 = 0.f;
    const int nfull = cnt >> 3;                              // groups of 8
    for (int g = part; g < nfull; g += GPART) {
        int4 a = *reinterpret_cast<const int4*>(lst + 8 * g);
        int4 b = *reinterpret_cast<const int4*>(lst + 8 * g + 4);
        s0 += Pb[a.x * 32]; s1 += Pb[a.y * 32];
        s2 += Pb[a.z * 32]; s3 += Pb[a.w * 32];
        s0 += Pb[b.x * 32]; s1 += Pb[b.y * 32];
        s2 += Pb[b.z * 32]; s3 += Pb[b.w * 32];
    }
    if (part == 0) {                                         // tail + deg
        for (int i = nfull * 8; i < cnt; i++) s0 += Pb[lst[i] * 32];
        if (lane == 0) g_Sdeg[e] = (float)cnt;
    }
    atomicAdd(&g_Ssum[(size_t)e * 32 + lane], (s0 + s1) + (s2 + s3));
}

// ---------------------------------------------------------------------------
// Kernel 4: per-edge KL from the [e][c] sums; masked mean via atomics.
// ---------------------------------------------------------------------------
__global__ void finalize_kernel(const void* __restrict__ e_mask) {
    int e = blockIdx.x * blockDim.x + threadIdx.x;
    int mode = (g_not_int01 == 0) ? 1 : ((g_not_f01 == 0) ? 2 : 0);
    bool sel = false;
    if (e < E) {
        if (mode == 1)      sel = ((const int*)e_mask)[e] != 0;
        else if (mode == 2) sel = ((const float*)e_mask)[e] != 0.0f;
        else                sel = ((const unsigned char*)e_mask)[e] != 0;
    }
    float kl = 0.f, cnt = 0.f;
    if (sel) {
        cnt = 1.f;
        float inv = 1.0f / (g_Sdeg[e] * TAUF);
#pragma unroll
        for (int c = 0; c < 16; c++) {
            float xs = g_Ssum[(size_t)e * 32 + c]      * inv + EPSF;
            float xt = g_Ssum[(size_t)e * 32 + 16 + c] * inv + EPSF;
            kl += xt * (logf(xt) - logf(xs));
        }
    }
#pragma unroll
    for (int off = 16; off; off >>= 1) {
        kl  += __shfl_down_sync(0xffffffffu, kl,  off);
        cnt += __shfl_down_sync(0xffffffffu, cnt, off);
    }
    if ((threadIdx.x & 31) == 0) {
        atomicAdd(&g_acc[0], kl);
        atomicAdd(&g_acc[1], cnt);
    }
}

__global__ void out_kernel(float* __restrict__ out) {
    out[0] = g_acc[0] / fmaxf(g_acc[1], 1.0f);
}

// ---------------------------------------------------------------------------
extern "C" void kernel_launch(void* const* d_in, const int* in_sizes, int n_in,
                              void* d_out, int out_size) {
    const float* pred_s = (const float*)d_in[0];
    const float* pred_t = (const float*)d_in[1];
    const float* H      = (const float*)d_in[2];
    const void*  e_mask = d_in[3];
    float* out = (float*)d_out;

    softmax_kernel<<<(V + 255) / 256, 256>>>(pred_s, pred_t);
    detect_mask_kernel<<<(E / 4 + 255) / 256, 256>>>((const unsigned int*)e_mask);
    build_kernel<<<dim3(NQT, NVC), 128>>>(H);
    gather_kernel<<<(E * GPART * 32 + 127) / 128, 128>>>();
    finalize_kernel<<<(E + 255) / 256, 256>>>(e_mask);
    out_kernel<<<1, 1>>>(out);
}

// round 10
// speedup vs baseline: 1.5620x; 1.5620x over previous
#include <cuda_runtime.h>
#include <cuda_fp16.h>
#include <math.h>

#define V 50000
#define E 5000
#define VCH 512             // v-chunk per CTA.y (all chunks incl. tail %16==0)
#define NVC 98              // 98*512 = 50176 >= V
#define NET 40              // edge tiles of 128 (40*128 = 5120 >= 5000)
#define CAP 1536            // per-edge list capacity (deg ~ 1001 +- 31)
#define SCAP 32             // per-lane staged hits per chunk (6.5 sigma of Binom(512,.02))
#define GPART 4             // warps cooperating per edge in gather
#define TAUF 0.5f
#define EPSF 1e-8f

// Scratch (__device__ globals; allocation-free rule)
__device__ __align__(16) __half g_Ph[(size_t)V * 32]; // packed softmax in fp16 [v][0..15]=ps,[16..31]=pt
__device__ int   g_cnt[E];                            // per-edge nonzero count (= deg_e)
__device__ __align__(16) int g_list[(size_t)E * CAP]; // per-edge vertex lists (unordered)
__device__ float g_Ssum[(size_t)E * 32];              // [e][c] channel sums (atomic-combined)
__device__ float g_Sdeg[E];                           // deg_e (float)
__device__ float g_acc[2];                            // {kl_sum, mask_count}
__device__ int   g_not_int01;                         // mask-dtype detection flags
__device__ int   g_not_f01;

// ---------------------------------------------------------------------------
// Kernel 1: softmax over C=16 for both preds -> packed fp16 rows (64 B each),
// plus zero per-replay state.
// ---------------------------------------------------------------------------
__device__ __forceinline__ void softmax16f(const float4* __restrict__ src, float* x) {
    float4 a[4];
#pragma unroll
    for (int i = 0; i < 4; i++) a[i] = src[i];
    const float* xi = reinterpret_cast<const float*>(a);
    float m = xi[0];
#pragma unroll
    for (int i = 1; i < 16; i++) m = fmaxf(m, xi[i]);
    float s = 0.f;
#pragma unroll
    for (int i = 0; i < 16; i++) { float e = expf(xi[i] - m); x[i] = e; s += e; }
    float r = 1.0f / s;
#pragma unroll
    for (int i = 0; i < 16; i++) x[i] *= r;
}

__global__ void softmax_kernel(const float* __restrict__ pred_s,
                               const float* __restrict__ pred_t) {
    int v = blockIdx.x * blockDim.x + threadIdx.x;
    int nthr = gridDim.x * blockDim.x;
    for (int i = v; i < E; i += nthr) g_cnt[i] = 0;
    for (int i = v; i < 32 * E; i += nthr) g_Ssum[i] = 0.f;
    if (v == 0) { g_acc[0] = 0.f; g_acc[1] = 0.f; g_not_int01 = 0; g_not_f01 = 0; }
    if (v >= V) return;
    float xs[16], xt[16];
    softmax16f(reinterpret_cast<const float4*>(pred_s + (size_t)v * 16), xs);
    softmax16f(reinterpret_cast<const float4*>(pred_t + (size_t)v * 16), xt);
    __half2* dst = reinterpret_cast<__half2*>(g_Ph + (size_t)v * 32);
#pragma unroll
    for (int i = 0; i < 8; i++) dst[i]     = __floats2half2_rn(xs[2 * i], xs[2 * i + 1]);
#pragma unroll
    for (int i = 0; i < 8; i++) dst[8 + i] = __floats2half2_rn(xt[2 * i], xt[2 * i + 1]);
}

// ---------------------------------------------------------------------------
// Kernel 1b: detect e_mask storage dtype (uint8 vs int32 vs float32).
// ---------------------------------------------------------------------------
__global__ void detect_mask_kernel(const unsigned int* __restrict__ mask_w) {
    int i = blockIdx.x * blockDim.x + threadIdx.x;
    if (i >= E / 4) return;
    unsigned int w = mask_w[i];
    if (w > 1u) atomicOr(&g_not_int01, 1);
    if (w != 0u && w != 0x3f800000u) atomicOr(&g_not_f01, 1);
}

// ---------------------------------------------------------------------------
// Kernel 2 (pass 1): the 1 GB stream. grid (NET, NVC), 128 thr, lane = edge
// (R8 shape -- the empirically fastest). Hits are staged into a padded smem
// buffer via STS (no return dependency in the hot loop); ONE atomicAdd + a
// burst flush per chunk replaces 5M in-chain ATOMG+STG pairs. Overflow
// beyond SCAP (prob ~1e-11 per lane-chunk) falls back to per-hit atomics,
// so correctness is unconditional.
// ---------------------------------------------------------------------------
__global__ void __launch_bounds__(128) build_kernel(const float* __restrict__ H) {
    __shared__ int sIdx[128 * (SCAP + 1)];           // pitch 33 -> conflict-free flush
    const int tid = threadIdx.x;
    int e = blockIdx.x * 128 + tid;
    const bool ev = (e < E);
    if (!ev) e = 0;                                  // clamped lanes read-only
    const int v0 = blockIdx.y * VCH;
    const int v1 = min(v0 + VCH, V);                 // chunk length always %16 == 0
    int* __restrict__ my = sIdx + tid * (SCAP + 1);
    int n = 0;

    const float* Hp = H + (size_t)v0 * E + e;
    for (int v = v0; v < v1; v += 16, Hp += (size_t)16 * E) {
        float h[16];
#pragma unroll
        for (int u = 0; u < 16; u++)                 // batch-issued: 2 KB/warp in flight
            h[u] = __ldg(Hp + (size_t)u * E);
#pragma unroll
        for (int u = 0; u < 16; u++) {
            if (ev && h[u] != 0.0f) {                // ~2% taken per lane-row
                if (n < SCAP) {
                    my[n++] = v + u;                 // STS: fire-and-forget
                } else {                             // astronomically rare fallback
                    int p = atomicAdd(&g_cnt[e], 1);
                    if (p < CAP) g_list[(size_t)e * CAP + p] = v + u;
                }
            }
        }
    }

    if (ev && n > 0) {                               // once per chunk
        int base = atomicAdd(&g_cnt[e], n);
        for (int i = 0; i < n; i++) {
            int p = base + i;
            if (p < CAP) g_list[(size_t)e * CAP + p] = my[i];
        }
    }
}

// ---------------------------------------------------------------------------
// Kernel 3 (pass 2): gather. GPART=4 warps per edge, lane = channel.
// P rows are fp16 (64 B/vertex -> halves L2 traffic vs fp32; gather was
// measured near the LTS cap). Warp p walks every-4th group of 8 int4-aligned
// list entries; math stays fp32 (convert-on-load), 4 rotating FADD chains,
// one atomicAdd per (e,c) to combine partitions.
// ---------------------------------------------------------------------------
__global__ void __launch_bounds__(128) gather_kernel() {
    const int gw   = (blockIdx.x * 128 + threadIdx.x) >> 5;  // global warp id
    const int lane = threadIdx.x & 31;                       // channel
    const int e    = gw >> 2;
    const int part = gw & (GPART - 1);
    if (e >= E) return;
    const int cnt = min(g_cnt[e], CAP);
    const int* __restrict__ lst = g_list + (size_t)e * CAP;
    const __half* __restrict__ Pb = g_Ph + lane;

    float s0 = 0.f, s1 = 0.f, s2 = 0.f, s3 = 0.f;
    const int nfull = cnt >> 3;                              // groups of 8
    for (int g = part; g < nfull; g += GPART) {
        int4 a = *reinterpret_cast<const int4*>(lst + 8 * g);
        int4 b = *reinterpret_cast<const int4*>(lst + 8 * g + 4);
        s0 += __half2float(Pb[a.x * 32]); s1 += __half2float(Pb[a.y * 32]);
        s2 += __half2float(Pb[a.z * 32]); s3 += __half2float(Pb[a.w * 32]);
        s0 += __half2float(Pb[b.x * 32]); s1 += __half2float(Pb[b.y * 32]);
        s2 += __half2float(Pb[b.z * 32]); s3 += __half2float(Pb[b.w * 32]);
    }
    if (part == 0) {                                         // tail + deg
        for (int i = nfull * 8; i < cnt; i++) s0 += __half2float(Pb[lst[i] * 32]);
        if (lane == 0) g_Sdeg[e] = (float)cnt;
    }
    atomicAdd(&g_Ssum[(size_t)e * 32 + lane], (s0 + s1) + (s2 + s3));
}

// ---------------------------------------------------------------------------
// Kernel 4: per-edge KL from the [e][c] sums; masked mean via atomics.
// ---------------------------------------------------------------------------
__global__ void finalize_kernel(const void* __restrict__ e_mask) {
    int e = blockIdx.x * blockDim.x + threadIdx.x;
    int mode = (g_not_int01 == 0) ? 1 : ((g_not_f01 == 0) ? 2 : 0);
    bool sel = false;
    if (e < E) {
        if (mode == 1)      sel = ((const int*)e_mask)[e] != 0;
        else if (mode == 2) sel = ((const float*)e_mask)[e] != 0.0f;
        else                sel = ((const unsigned char*)e_mask)[e] != 0;
    }
    float kl = 0.f, cnt = 0.f;
    if (sel) {
        cnt = 1.f;
        float inv = 1.0f / (g_Sdeg[e] * TAUF);
#pragma unroll
        for (int c = 0; c < 16; c++) {
            float xs = g_Ssum[(size_t)e * 32 + c]      * inv + EPSF;
            float xt = g_Ssum[(size_t)e * 32 + 16 + c] * inv + EPSF;
            kl += xt * (logf(xt) - logf(xs));
        }
    }
#pragma unroll
    for (int off = 16; off; off >>= 1) {
        kl  += __shfl_down_sync(0xffffffffu, kl,  off);
        cnt += __shfl_down_sync(0xffffffffu, cnt, off);
    }
    if ((threadIdx.x & 31) == 0) {
        atomicAdd(&g_acc[0], kl);
        atomicAdd(&g_acc[1], cnt);
    }
}

__global__ void out_kernel(float* __restrict__ out) {
    out[0] = g_acc[0] / fmaxf(g_acc[1], 1.0f);
}

// ---------------------------------------------------------------------------
extern "C" void kernel_launch(void* const* d_in, const int* in_sizes, int n_in,
                              void* d_out, int out_size) {
    const float* pred_s = (const float*)d_in[0];
    const float* pred_t = (const float*)d_in[1];
    const float* H      = (const float*)d_in[2];
    const void*  e_mask = d_in[3];
    float* out = (float*)d_out;

    softmax_kernel<<<(V + 255) / 256, 256>>>(pred_s, pred_t);
    detect_mask_kernel<<<(E / 4 + 255) / 256, 256>>>((const unsigned int*)e_mask);
    build_kernel<<<dim3(NET, NVC), 128>>>(H);
    gather_kernel<<<(E * GPART * 32 + 127) / 128, 128>>>();
    finalize_kernel<<<(E + 255) / 256, 256>>>(e_mask);
    out_kernel<<<1, 1>>>(out);
}